// round 16
// baseline (speedup 1.0000x reference)
#include <cuda_runtime.h>
#include <cuda_fp16.h>
#include <cstdint>

#define D_DIM    256
#define NBC      10
#define MAX_M    1024
#define MAX_N    100000
#define MAX_NP   100096
#define CAP      2048
#define MARGIN   0.03f
#define KC       64
#define ASTRIDE  72      // fp16 elems per smem row (64 + 8 pad)

#define A_BYTES      36864                    // 256 x 72 x 2
#define B_BYTES      18432                    // 128 x 72 x 2
#define STAGE_BYTES  (A_BYTES + B_BYTES)      // 55296
#define SM_NX        (2 * STAGE_BYTES)        // 110592
#define SMEM_BYTES   (SM_NX + 512)            // 111104 -> 2 CTAs/SM

__device__ float              g_xq[MAX_M * D_DIM];
__device__ unsigned short     g_qb[MAX_M * D_DIM];          // fp16 bits
__device__ unsigned short     g_Xb[(size_t)MAX_NP * D_DIM]; // fp16 bits, pad rows 0
__device__ float              g_nx2[MAX_N];
__device__ unsigned long long g_min[MAX_M];
__device__ int                g_cnum[MAX_M];
__device__ int                g_cand[MAX_M * CAP];

__device__ __forceinline__ unsigned f2ord(float f) {
    unsigned u = __float_as_uint(f);
    return (u & 0x80000000u) ? ~u : (u | 0x80000000u);
}
__device__ __forceinline__ float ord2f(unsigned o) {
    return __uint_as_float((o & 0x80000000u) ? (o ^ 0x80000000u) : ~o);
}
__device__ __forceinline__ unsigned smem_u32(const void* p) {
    unsigned a;
    asm("{ .reg .u64 t; cvta.to.shared.u64 t, %1; cvt.u32.u64 %0, t; }" : "=r"(a) : "l"(p));
    return a;
}
__device__ __forceinline__ void cp16(unsigned dst, const void* src) {
    asm volatile("cp.async.cg.shared.global [%0], [%1], 16;" :: "r"(dst), "l"(src));
}
#define CP_COMMIT() asm volatile("cp.async.commit_group;" ::: "memory")
#define CP_WAIT(n)  asm volatile("cp.async.wait_group %0;" :: "n"(n) : "memory")

__device__ __forceinline__ void ldsm_x4(unsigned& r0, unsigned& r1, unsigned& r2, unsigned& r3, unsigned addr) {
    asm volatile("ldmatrix.sync.aligned.m8n8.x4.shared.b16 {%0,%1,%2,%3}, [%4];"
        : "=r"(r0), "=r"(r1), "=r"(r2), "=r"(r3) : "r"(addr));
}
__device__ __forceinline__ void mma16816h(unsigned* c, const unsigned* a, unsigned b0, unsigned b1) {
    asm volatile(
        "mma.sync.aligned.m16n8k16.row.col.f16.f16.f16.f16 "
        "{%0,%1}, {%2,%3,%4,%5}, {%6,%7}, {%0,%1};"
        : "+r"(c[0]), "+r"(c[1])
        : "r"(a[0]), "r"(a[1]), "r"(a[2]), "r"(a[3]), "r"(b0), "r"(b1));
}

// ---------------------------------------------------------------------------
// 1) fused prep: blocks [0, cvt_blocks) convert X rows (8 per block, warp/row);
//    blocks [cvt_blocks, cvt_blocks+M) normalize queries + reset state.
// ---------------------------------------------------------------------------
__global__ void prep_kernel(const float* __restrict__ X, int N, int cvt_blocks,
                            const float* __restrict__ x,
                            const float* __restrict__ center, int M) {
    int b = blockIdx.x, t = threadIdx.x;
    if (b < cvt_blocks) {
        int w = (b * 256 + t) >> 5;
        int lane = t & 31;
        if (w >= N) return;
        const float4* row = (const float4*)(X + (size_t)w * D_DIM);
        float4 v0 = row[lane * 2], v1 = row[lane * 2 + 1];
        float s = v0.x*v0.x + v0.y*v0.y + v0.z*v0.z + v0.w*v0.w
                + v1.x*v1.x + v1.y*v1.y + v1.z*v1.z + v1.w*v1.w;
        #pragma unroll
        for (int o = 16; o > 0; o >>= 1) s += __shfl_xor_sync(0xffffffffu, s, o);
        if (lane == 0) g_nx2[w] = s;
        uint4 o4;
        o4.x = __half_as_ushort(__float2half_rn(v0.x)) | ((unsigned)__half_as_ushort(__float2half_rn(v0.y)) << 16);
        o4.y = __half_as_ushort(__float2half_rn(v0.z)) | ((unsigned)__half_as_ushort(__float2half_rn(v0.w)) << 16);
        o4.z = __half_as_ushort(__float2half_rn(v1.x)) | ((unsigned)__half_as_ushort(__float2half_rn(v1.y)) << 16);
        o4.w = __half_as_ushort(__float2half_rn(v1.z)) | ((unsigned)__half_as_ushort(__float2half_rn(v1.w)) << 16);
        ((uint4*)(g_Xb + (size_t)w * D_DIM))[lane] = o4;
    } else {
        int q = b - cvt_blocks;
        if (q >= M) return;
        if (t == 0) { g_min[q] = ~0ull; g_cnum[q] = 0; }
        float v = x[q * D_DIM + t];
        float s = v * v;
        __shared__ float red[8];
        #pragma unroll
        for (int o = 16; o > 0; o >>= 1) s += __shfl_xor_sync(0xffffffffu, s, o);
        if ((t & 31) == 0) red[t >> 5] = s;
        __syncthreads();
        if (t < 8) {
            float r = red[t];
            #pragma unroll
            for (int o = 4; o > 0; o >>= 1) r += __shfl_xor_sync(0xffu, r, o);
            if (t == 0) red[0] = r;
        }
        __syncthreads();
        float val = v / sqrtf(red[0]) - center[t];
        g_xq[q * D_DIM + t] = val;
        g_qb[q * D_DIM + t] = __half_as_ushort(__float2half_rn(val));
    }
}

// ---------------------------------------------------------------------------
// 2) persistent fp16 mma.sync GEMM: grid (4, 74) = 296 CTAs = 2/SM,
//    each CTA loops n-tiles by+74*it; cross-tile chunk prefetch keeps the
//    cp.async pipeline continuously full.
// ---------------------------------------------------------------------------
__device__ __forceinline__ void load_chunk(unsigned stage, int m0, int n0,
                                           int kc, int tid) {
    #pragma unroll
    for (int r = 0; r < 8; r++) {
        int idx = tid + 256 * r;
        int row = idx >> 3, g = idx & 7;
        cp16(stage + (row * ASTRIDE + g * 8) * 2,
             g_qb + (size_t)(m0 + row) * D_DIM + kc + g * 8);
    }
    #pragma unroll
    for (int r = 0; r < 4; r++) {
        int idx = tid + 256 * r;
        int row = idx >> 3, g = idx & 7;
        cp16(stage + A_BYTES + (row * ASTRIDE + g * 8) * 2,
             g_Xb + (size_t)(n0 + row) * D_DIM + kc + g * 8);
    }
}

__global__ __launch_bounds__(256, 2)
void gemm_kernel(int N, int M, int ntiles) {
    extern __shared__ char sm[];
    float* nxs = (float*)(sm + SM_NX);
    unsigned smu = smem_u32(sm);

    int tid = threadIdx.x;
    int w = tid >> 5, lane = tid & 31;
    int wm = w >> 1, wn = w & 1;
    int m0 = blockIdx.x * 256;
    int stride = gridDim.y;

    unsigned aoff = (unsigned)(((wm * 64 + (lane & 15)) * ASTRIDE + (lane >> 4) * 8) * 2);
    unsigned boff = (unsigned)(A_BYTES +
        ((wn * 64 + ((lane >> 4) & 1) * 8 + (lane & 7)) * ASTRIDE + ((lane >> 3) & 1) * 8) * 2);
    int r = lane >> 2, qp = lane & 3;

    unsigned c[4][8][2];
    #pragma unroll
    for (int mi = 0; mi < 4; mi++)
        #pragma unroll
        for (int ni = 0; ni < 8; ni++) { c[mi][ni][0] = 0u; c[mi][ni][1] = 0u; }

    int nt0 = blockIdx.y;
    if (nt0 < ntiles) {
        load_chunk(smu, m0, nt0 * 128, 0, tid);   // chunk0 of first tile -> buf 0
        CP_COMMIT();
    }

    for (int nt = nt0; nt < ntiles; nt += stride) {
        int n0 = nt * 128;
        int next_nt = nt + stride;
        __syncthreads();                           // epilogue readers done before nxs rewrite
        if (tid < 128) {
            int gn = n0 + tid;
            nxs[tid] = (gn < N) ? g_nx2[gn] : 1e30f;
        }

        #pragma unroll
        for (int kc = 0; kc < 4; kc++) {
            int buf = kc & 1;
            if (kc < 3) {
                load_chunk(smu + (buf ^ 1) * STAGE_BYTES, m0, n0, (kc + 1) * KC, tid);
                CP_COMMIT();
                CP_WAIT(1);
            } else if (next_nt < ntiles) {
                load_chunk(smu + (buf ^ 1) * STAGE_BYTES, m0, next_nt * 128, 0, tid);
                CP_COMMIT();
                CP_WAIT(1);
            } else {
                CP_WAIT(0);
            }
            __syncthreads();

            unsigned stage = smu + buf * STAGE_BYTES;
            unsigned Au = stage + aoff;
            unsigned Bu = stage + boff;
            #pragma unroll
            for (int ks = 0; ks < 4; ks++) {
                unsigned a[4][4];
                #pragma unroll
                for (int mi = 0; mi < 4; mi++)
                    ldsm_x4(a[mi][0], a[mi][1], a[mi][2], a[mi][3],
                            Au + mi * (16 * ASTRIDE * 2) + ks * 32);
                unsigned b[4][4];
                #pragma unroll
                for (int p = 0; p < 4; p++)
                    ldsm_x4(b[p][0], b[p][1], b[p][2], b[p][3],
                            Bu + p * (16 * ASTRIDE * 2) + ks * 32);
                #pragma unroll
                for (int mi = 0; mi < 4; mi++)
                    #pragma unroll
                    for (int p = 0; p < 4; p++) {
                        mma16816h(c[mi][2 * p + 0], a[mi], b[p][0], b[p][1]);
                        mma16816h(c[mi][2 * p + 1], a[mi], b[p][2], b[p][3]);
                    }
            }
            __syncthreads();
        }

        // ---- epilogue for tile nt: argmin + margin candidates, reset acc ----
        #pragma unroll
        for (int mi = 0; mi < 4; mi++) {
            #pragma unroll
            for (int h = 0; h < 2; h++) {
                int lrow = wm * 64 + mi * 16 + h * 8 + r;
                int q = m0 + lrow;
                unsigned long long kmin = ~0ull;
                #pragma unroll
                for (int ni = 0; ni < 8; ni++) {
                    int lc = wn * 64 + ni * 8 + 2 * qp;
                    float2 d = __half22float2(*(const __half2*)&c[mi][ni][h]);
                    float s0 = fmaf(-2.f, d.x, nxs[lc]);
                    float s1 = fmaf(-2.f, d.y, nxs[lc + 1]);
                    unsigned long long k0 = ((unsigned long long)f2ord(s0) << 32) | (unsigned)(n0 + lc);
                    unsigned long long k1 = ((unsigned long long)f2ord(s1) << 32) | (unsigned)(n0 + lc + 1);
                    if (k0 < kmin) kmin = k0;
                    if (k1 < kmin) kmin = k1;
                }
                unsigned long long o1 = __shfl_xor_sync(0xffffffffu, kmin, 1);
                if (o1 < kmin) kmin = o1;
                unsigned long long o2 = __shfl_xor_sync(0xffffffffu, kmin, 2);
                if (o2 < kmin) kmin = o2;

                float thr = 0.f;
                if (qp == 0 && q < M) {
                    unsigned long long old = atomicMin(&g_min[q], kmin);
                    unsigned long long cur = (old < kmin) ? old : kmin;
                    thr = ord2f((unsigned)(cur >> 32)) + MARGIN;
                }
                thr = __shfl_sync(0xffffffffu, thr, lane & ~3);

                if (q < M) {
                    #pragma unroll
                    for (int ni = 0; ni < 8; ni++) {
                        int lc = wn * 64 + ni * 8 + 2 * qp;
                        float2 d = __half22float2(*(const __half2*)&c[mi][ni][h]);
                        float s0 = fmaf(-2.f, d.x, nxs[lc]);
                        float s1 = fmaf(-2.f, d.y, nxs[lc + 1]);
                        if (s0 < thr) {
                            int p = atomicAdd(&g_cnum[q], 1);
                            if (p < CAP) g_cand[q * CAP + p] = n0 + lc;
                        }
                        if (s1 < thr) {
                            int p = atomicAdd(&g_cnum[q], 1);
                            if (p < CAP) g_cand[q * CAP + p] = n0 + lc + 1;
                        }
                    }
                }
                c[mi][0][h] = 0u;   // partial reset below covers all
            }
        }
        #pragma unroll
        for (int mi = 0; mi < 4; mi++)
            #pragma unroll
            for (int ni = 0; ni < 8; ni++) { c[mi][ni][0] = 0u; c[mi][ni][1] = 0u; }
    }
}

// ---------------------------------------------------------------------------
// 3) fused post: exact fp32 rescore + labels + conformal p-values + creds
// ---------------------------------------------------------------------------
__global__ void post_kernel(const float* __restrict__ X,
                            const int* __restrict__ labels,
                            const int* __restrict__ tni,
                            const int* __restrict__ cali,
                            float* __restrict__ out,
                            int M, int ncali, int Kn) {
    __shared__ float xq[D_DIM];
    __shared__ unsigned long long wmin[8];
    __shared__ int scali[1024];
    __shared__ int cnt[NBC];
    __shared__ int sclosest;
    int q = blockIdx.x;
    int tid = threadIdx.x, w = tid >> 5, lane = tid & 31;

    xq[tid] = g_xq[q * D_DIM + tid];
    for (int i = tid; i < ncali; i += 256) scali[i] = cali[i];
    if (tid < NBC) cnt[tid] = 0;
    int cnum = min(g_cnum[q], CAP);
    __syncthreads();

    unsigned long long key = ~0ull;
    for (int c = w; c < cnum; c += 8) {
        int gn = g_cand[q * CAP + c];
        const float4* row = (const float4*)(X + (size_t)gn * D_DIM);
        const float4* xv = (const float4*)xq;
        float4 v0 = row[lane * 2], v1 = row[lane * 2 + 1];
        float4 a0 = xv[lane * 2], a1 = xv[lane * 2 + 1];
        float dp = v0.x*a0.x + v0.y*a0.y + v0.z*a0.z + v0.w*a0.w
                 + v1.x*a1.x + v1.y*a1.y + v1.z*a1.z + v1.w*a1.w;
        #pragma unroll
        for (int o = 16; o > 0; o >>= 1) dp += __shfl_xor_sync(0xffffffffu, dp, o);
        float s = g_nx2[gn] - 2.f * dp;
        unsigned long long k = ((unsigned long long)f2ord(s) << 32) | (unsigned)gn;
        if (k < key) key = k;
    }
    if (lane == 0) wmin[w] = key;
    __syncthreads();
    if (tid == 0) {
        unsigned long long best = wmin[0];
        #pragma unroll
        for (int i = 1; i < 8; i++) if (wmin[i] < best) best = wmin[i];
        sclosest = (int)(best & 0xffffffffull);
    }
    __syncthreads();

    int closest = sclosest;
    for (int e = tid; e < Kn; e += 256) {
        int idx = (e == 0) ? closest : tni[(size_t)closest * (Kn - 1) + (e - 1)];
        atomicAdd(&cnt[labels[idx]], 1);
    }
    __syncthreads();

    if (tid < 32) {
        int kkey = 0x7fffffff;
        if (lane < NBC) {
            int v = Kn - cnt[lane];
            int lo = 0, hi = ncali;
            while (lo < hi) {
                int mid = (lo + hi) >> 1;
                if (scali[mid] < v) lo = mid + 1; else hi = mid;
            }
            kkey = lo * 16 + lane;
        }
        #pragma unroll
        for (int o = 16; o > 0; o >>= 1)
            kkey = min(kkey, __shfl_xor_sync(0xffffffffu, kkey, o));
        if (lane == 0) {
            int pred = kkey & 15, pos = kkey >> 4;
            float pmax = (float)(ncali - pos) / (float)ncali;
            #pragma unroll
            for (int c = 0; c < NBC; c++)
                out[q * NBC + c] = (c == pred) ? pmax : 0.f;
        }
    }
}

// ---------------------------------------------------------------------------
extern "C" void kernel_launch(void* const* d_in, const int* in_sizes, int n_in,
                              void* d_out, int out_size) {
    const float* x      = (const float*)d_in[0];
    const float* X      = (const float*)d_in[1];
    const float* center = (const float*)d_in[2];
    const int*   labels = (const int*)d_in[3];
    const int*   tni    = (const int*)d_in[4];
    const int*   cali   = (const int*)d_in[5];
    float*       out    = (float*)d_out;

    int d      = in_sizes[2];
    int M      = in_sizes[0] / d;
    int N      = in_sizes[3];
    int ncali  = in_sizes[5];
    int Kn     = in_sizes[4] / N + 1;
    int ntiles = (N + 127) / 128;

    cudaFuncSetAttribute(gemm_kernel, cudaFuncAttributeMaxDynamicSharedMemorySize, SMEM_BYTES);

    int cvt_blocks = (N + 7) / 8;
    prep_kernel<<<cvt_blocks + M, 256>>>(X, N, cvt_blocks, x, center, M);

    int gy = (ntiles < 74) ? ntiles : 74;
    dim3 grid((M + 255) / 256, gy);
    gemm_kernel<<<grid, 256, SMEM_BYTES>>>(N, M, ntiles);

    post_kernel<<<M, 256>>>(X, labels, tni, cali, out, M, ncali, Kn);
}

// round 17
// speedup vs baseline: 1.1581x; 1.1581x over previous
#include <cuda_runtime.h>
#include <cuda_fp16.h>
#include <cstdint>

#define D_DIM    256
#define NBC      10
#define MAX_M    1024
#define MAX_N    100000
#define MAX_NP   100096
#define CAP      2048
#define MARGIN   0.03f
#define KC       64
#define ASTRIDE  72      // fp16 elems per smem row (64 + 8 pad)

#define A_BYTES      36864                    // 256 x 72 x 2
#define B_BYTES      18432                    // 128 x 72 x 2
#define STAGE_BYTES  (A_BYTES + B_BYTES)      // 55296
#define SM_NX        (2 * STAGE_BYTES)        // 110592
#define SMEM_BYTES   (SM_NX + 512)            // 111104 -> 2 CTAs/SM

__device__ float              g_xq[MAX_M * D_DIM];
__device__ unsigned short     g_qb[MAX_M * D_DIM];          // fp16 bits
__device__ unsigned short     g_Xb[(size_t)MAX_NP * D_DIM]; // fp16 bits, pad rows 0
__device__ float              g_nx2[MAX_N];
__device__ unsigned long long g_min[MAX_M];
__device__ int                g_cnum[MAX_M];
__device__ int                g_cand[MAX_M * CAP];

__device__ __forceinline__ unsigned f2ord(float f) {
    unsigned u = __float_as_uint(f);
    return (u & 0x80000000u) ? ~u : (u | 0x80000000u);
}
__device__ __forceinline__ float ord2f(unsigned o) {
    return __uint_as_float((o & 0x80000000u) ? (o ^ 0x80000000u) : ~o);
}
__device__ __forceinline__ unsigned smem_u32(const void* p) {
    unsigned a;
    asm("{ .reg .u64 t; cvta.to.shared.u64 t, %1; cvt.u32.u64 %0, t; }" : "=r"(a) : "l"(p));
    return a;
}
__device__ __forceinline__ void cp16(unsigned dst, const void* src) {
    asm volatile("cp.async.cg.shared.global [%0], [%1], 16;" :: "r"(dst), "l"(src));
}
#define CP_COMMIT() asm volatile("cp.async.commit_group;" ::: "memory")
#define CP_WAIT(n)  asm volatile("cp.async.wait_group %0;" :: "n"(n) : "memory")

__device__ __forceinline__ void ldsm_x4(unsigned& r0, unsigned& r1, unsigned& r2, unsigned& r3, unsigned addr) {
    asm volatile("ldmatrix.sync.aligned.m8n8.x4.shared.b16 {%0,%1,%2,%3}, [%4];"
        : "=r"(r0), "=r"(r1), "=r"(r2), "=r"(r3) : "r"(addr));
}
__device__ __forceinline__ void mma16816h(unsigned* c, const unsigned* a, unsigned b0, unsigned b1) {
    asm volatile(
        "mma.sync.aligned.m16n8k16.row.col.f16.f16.f16.f16 "
        "{%0,%1}, {%2,%3,%4,%5}, {%6,%7}, {%0,%1};"
        : "+r"(c[0]), "+r"(c[1])
        : "r"(a[0]), "r"(a[1]), "r"(a[2]), "r"(a[3]), "r"(b0), "r"(b1));
}

// ---------------------------------------------------------------------------
// 1) fused prep: blocks [0, cvt_blocks) convert X rows (8 per block, warp/row);
//    blocks [cvt_blocks, cvt_blocks+M) normalize queries + reset state.
// ---------------------------------------------------------------------------
__global__ void prep_kernel(const float* __restrict__ X, int N, int cvt_blocks,
                            const float* __restrict__ x,
                            const float* __restrict__ center, int M) {
    int b = blockIdx.x, t = threadIdx.x;
    if (b < cvt_blocks) {
        int w = (b * 256 + t) >> 5;
        int lane = t & 31;
        if (w >= N) return;
        const float4* row = (const float4*)(X + (size_t)w * D_DIM);
        float4 v0 = row[lane * 2], v1 = row[lane * 2 + 1];
        float s = v0.x*v0.x + v0.y*v0.y + v0.z*v0.z + v0.w*v0.w
                + v1.x*v1.x + v1.y*v1.y + v1.z*v1.z + v1.w*v1.w;
        #pragma unroll
        for (int o = 16; o > 0; o >>= 1) s += __shfl_xor_sync(0xffffffffu, s, o);
        if (lane == 0) g_nx2[w] = s;
        uint4 o4;
        o4.x = __half_as_ushort(__float2half_rn(v0.x)) | ((unsigned)__half_as_ushort(__float2half_rn(v0.y)) << 16);
        o4.y = __half_as_ushort(__float2half_rn(v0.z)) | ((unsigned)__half_as_ushort(__float2half_rn(v0.w)) << 16);
        o4.z = __half_as_ushort(__float2half_rn(v1.x)) | ((unsigned)__half_as_ushort(__float2half_rn(v1.y)) << 16);
        o4.w = __half_as_ushort(__float2half_rn(v1.z)) | ((unsigned)__half_as_ushort(__float2half_rn(v1.w)) << 16);
        ((uint4*)(g_Xb + (size_t)w * D_DIM))[lane] = o4;
    } else {
        int q = b - cvt_blocks;
        if (q >= M) return;
        if (t == 0) { g_min[q] = ~0ull; g_cnum[q] = 0; }
        float v = x[q * D_DIM + t];
        float s = v * v;
        __shared__ float red[8];
        #pragma unroll
        for (int o = 16; o > 0; o >>= 1) s += __shfl_xor_sync(0xffffffffu, s, o);
        if ((t & 31) == 0) red[t >> 5] = s;
        __syncthreads();
        if (t < 8) {
            float r = red[t];
            #pragma unroll
            for (int o = 4; o > 0; o >>= 1) r += __shfl_xor_sync(0xffu, r, o);
            if (t == 0) red[0] = r;
        }
        __syncthreads();
        float val = v / sqrtf(red[0]) - center[t];
        g_xq[q * D_DIM + t] = val;
        g_qb[q * D_DIM + t] = __half_as_ushort(__float2half_rn(val));
    }
}

// ---------------------------------------------------------------------------
// 2) fp16 mma.sync GEMM (R12 proven): CTA 256x128, warp m64xn64, f16 acc
// ---------------------------------------------------------------------------
__device__ __forceinline__ void load_chunk(unsigned stage, int m0, int n0,
                                           int kc, int tid) {
    #pragma unroll
    for (int r = 0; r < 8; r++) {
        int idx = tid + 256 * r;
        int row = idx >> 3, g = idx & 7;
        cp16(stage + (row * ASTRIDE + g * 8) * 2,
             g_qb + (size_t)(m0 + row) * D_DIM + kc + g * 8);
    }
    #pragma unroll
    for (int r = 0; r < 4; r++) {
        int idx = tid + 256 * r;
        int row = idx >> 3, g = idx & 7;
        cp16(stage + A_BYTES + (row * ASTRIDE + g * 8) * 2,
             g_Xb + (size_t)(n0 + row) * D_DIM + kc + g * 8);
    }
}

__global__ __launch_bounds__(256, 2)
void gemm_kernel(int N, int M) {
    extern __shared__ char sm[];
    float* nxs = (float*)(sm + SM_NX);
    unsigned smu = smem_u32(sm);

    int tid = threadIdx.x;
    int w = tid >> 5, lane = tid & 31;
    int wm = w >> 1, wn = w & 1;
    int m0 = blockIdx.x * 256;
    int n0 = blockIdx.y * 128;

    if (tid < 128) {
        int gn = n0 + tid;
        nxs[tid] = (gn < N) ? g_nx2[gn] : 1e30f;
    }

    unsigned c[4][8][2];
    #pragma unroll
    for (int mi = 0; mi < 4; mi++)
        #pragma unroll
        for (int ni = 0; ni < 8; ni++) { c[mi][ni][0] = 0u; c[mi][ni][1] = 0u; }

    unsigned aoff = (unsigned)(((wm * 64 + (lane & 15)) * ASTRIDE + (lane >> 4) * 8) * 2);
    unsigned boff = (unsigned)(A_BYTES +
        ((wn * 64 + ((lane >> 4) & 1) * 8 + (lane & 7)) * ASTRIDE + ((lane >> 3) & 1) * 8) * 2);

    load_chunk(smu, m0, n0, 0, tid);
    CP_COMMIT();

    #pragma unroll
    for (int kc = 0; kc < 4; kc++) {
        int buf = kc & 1;
        if (kc < 3) {
            load_chunk(smu + (buf ^ 1) * STAGE_BYTES, m0, n0, (kc + 1) * KC, tid);
            CP_COMMIT();
            CP_WAIT(1);
        } else {
            CP_WAIT(0);
        }
        __syncthreads();

        unsigned stage = smu + buf * STAGE_BYTES;
        unsigned Au = stage + aoff;
        unsigned Bu = stage + boff;
        #pragma unroll
        for (int ks = 0; ks < 4; ks++) {
            unsigned a[4][4];
            #pragma unroll
            for (int mi = 0; mi < 4; mi++)
                ldsm_x4(a[mi][0], a[mi][1], a[mi][2], a[mi][3],
                        Au + mi * (16 * ASTRIDE * 2) + ks * 32);
            unsigned b[4][4];
            #pragma unroll
            for (int p = 0; p < 4; p++)
                ldsm_x4(b[p][0], b[p][1], b[p][2], b[p][3],
                        Bu + p * (16 * ASTRIDE * 2) + ks * 32);
            #pragma unroll
            for (int mi = 0; mi < 4; mi++)
                #pragma unroll
                for (int p = 0; p < 4; p++) {
                    mma16816h(c[mi][2 * p + 0], a[mi], b[p][0], b[p][1]);
                    mma16816h(c[mi][2 * p + 1], a[mi], b[p][2], b[p][3]);
                }
        }
        __syncthreads();
    }

    int r = lane >> 2, qp = lane & 3;
    #pragma unroll
    for (int mi = 0; mi < 4; mi++) {
        #pragma unroll
        for (int h = 0; h < 2; h++) {
            int lrow = wm * 64 + mi * 16 + h * 8 + r;
            int q = m0 + lrow;
            unsigned long long kmin = ~0ull;
            #pragma unroll
            for (int ni = 0; ni < 8; ni++) {
                int lc = wn * 64 + ni * 8 + 2 * qp;
                float2 d = __half22float2(*(const __half2*)&c[mi][ni][h]);
                float s0 = fmaf(-2.f, d.x, nxs[lc]);
                float s1 = fmaf(-2.f, d.y, nxs[lc + 1]);
                unsigned long long k0 = ((unsigned long long)f2ord(s0) << 32) | (unsigned)(n0 + lc);
                unsigned long long k1 = ((unsigned long long)f2ord(s1) << 32) | (unsigned)(n0 + lc + 1);
                if (k0 < kmin) kmin = k0;
                if (k1 < kmin) kmin = k1;
            }
            unsigned long long o1 = __shfl_xor_sync(0xffffffffu, kmin, 1);
            if (o1 < kmin) kmin = o1;
            unsigned long long o2 = __shfl_xor_sync(0xffffffffu, kmin, 2);
            if (o2 < kmin) kmin = o2;

            float thr = 0.f;
            if (qp == 0 && q < M) {
                unsigned long long old = atomicMin(&g_min[q], kmin);
                unsigned long long cur = (old < kmin) ? old : kmin;
                thr = ord2f((unsigned)(cur >> 32)) + MARGIN;
            }
            thr = __shfl_sync(0xffffffffu, thr, lane & ~3);

            if (q < M) {
                #pragma unroll
                for (int ni = 0; ni < 8; ni++) {
                    int lc = wn * 64 + ni * 8 + 2 * qp;
                    float2 d = __half22float2(*(const __half2*)&c[mi][ni][h]);
                    float s0 = fmaf(-2.f, d.x, nxs[lc]);
                    float s1 = fmaf(-2.f, d.y, nxs[lc + 1]);
                    if (s0 < thr) {
                        int p = atomicAdd(&g_cnum[q], 1);
                        if (p < CAP) g_cand[q * CAP + p] = n0 + lc;
                    }
                    if (s1 < thr) {
                        int p = atomicAdd(&g_cnum[q], 1);
                        if (p < CAP) g_cand[q * CAP + p] = n0 + lc + 1;
                    }
                }
            }
        }
    }
}

// ---------------------------------------------------------------------------
// 3) fused post: exact fp32 rescore + labels + conformal p-values + creds
// ---------------------------------------------------------------------------
__global__ void post_kernel(const float* __restrict__ X,
                            const int* __restrict__ labels,
                            const int* __restrict__ tni,
                            const int* __restrict__ cali,
                            float* __restrict__ out,
                            int M, int ncali, int Kn) {
    __shared__ float xq[D_DIM];
    __shared__ unsigned long long wmin[8];
    __shared__ int scali[1024];
    __shared__ int cnt[NBC];
    __shared__ int sclosest;
    int q = blockIdx.x;
    int tid = threadIdx.x, w = tid >> 5, lane = tid & 31;

    xq[tid] = g_xq[q * D_DIM + tid];
    for (int i = tid; i < ncali; i += 256) scali[i] = cali[i];
    if (tid < NBC) cnt[tid] = 0;
    int cnum = min(g_cnum[q], CAP);
    __syncthreads();

    unsigned long long key = ~0ull;
    for (int c = w; c < cnum; c += 8) {
        int gn = g_cand[q * CAP + c];
        const float4* row = (const float4*)(X + (size_t)gn * D_DIM);
        const float4* xv = (const float4*)xq;
        float4 v0 = row[lane * 2], v1 = row[lane * 2 + 1];
        float4 a0 = xv[lane * 2], a1 = xv[lane * 2 + 1];
        float dp = v0.x*a0.x + v0.y*a0.y + v0.z*a0.z + v0.w*a0.w
                 + v1.x*a1.x + v1.y*a1.y + v1.z*a1.z + v1.w*a1.w;
        #pragma unroll
        for (int o = 16; o > 0; o >>= 1) dp += __shfl_xor_sync(0xffffffffu, dp, o);
        float s = g_nx2[gn] - 2.f * dp;
        unsigned long long k = ((unsigned long long)f2ord(s) << 32) | (unsigned)gn;
        if (k < key) key = k;
    }
    if (lane == 0) wmin[w] = key;
    __syncthreads();
    if (tid == 0) {
        unsigned long long best = wmin[0];
        #pragma unroll
        for (int i = 1; i < 8; i++) if (wmin[i] < best) best = wmin[i];
        sclosest = (int)(best & 0xffffffffull);
    }
    __syncthreads();

    int closest = sclosest;
    for (int e = tid; e < Kn; e += 256) {
        int idx = (e == 0) ? closest : tni[(size_t)closest * (Kn - 1) + (e - 1)];
        atomicAdd(&cnt[labels[idx]], 1);
    }
    __syncthreads();

    if (tid < 32) {
        int kkey = 0x7fffffff;
        if (lane < NBC) {
            int v = Kn - cnt[lane];
            int lo = 0, hi = ncali;
            while (lo < hi) {
                int mid = (lo + hi) >> 1;
                if (scali[mid] < v) lo = mid + 1; else hi = mid;
            }
            kkey = lo * 16 + lane;
        }
        #pragma unroll
        for (int o = 16; o > 0; o >>= 1)
            kkey = min(kkey, __shfl_xor_sync(0xffffffffu, kkey, o));
        if (lane == 0) {
            int pred = kkey & 15, pos = kkey >> 4;
            float pmax = (float)(ncali - pos) / (float)ncali;
            #pragma unroll
            for (int c = 0; c < NBC; c++)
                out[q * NBC + c] = (c == pred) ? pmax : 0.f;
        }
    }
}

// ---------------------------------------------------------------------------
extern "C" void kernel_launch(void* const* d_in, const int* in_sizes, int n_in,
                              void* d_out, int out_size) {
    const float* x      = (const float*)d_in[0];
    const float* X      = (const float*)d_in[1];
    const float* center = (const float*)d_in[2];
    const int*   labels = (const int*)d_in[3];
    const int*   tni    = (const int*)d_in[4];
    const int*   cali   = (const int*)d_in[5];
    float*       out    = (float*)d_out;

    int d      = in_sizes[2];
    int M      = in_sizes[0] / d;
    int N      = in_sizes[3];
    int ncali  = in_sizes[5];
    int Kn     = in_sizes[4] / N + 1;

    cudaFuncSetAttribute(gemm_kernel, cudaFuncAttributeMaxDynamicSharedMemorySize, SMEM_BYTES);

    int cvt_blocks = (N + 7) / 8;
    prep_kernel<<<cvt_blocks + M, 256>>>(X, N, cvt_blocks, x, center, M);

    dim3 grid((M + 255) / 256, (N + 127) / 128);
    gemm_kernel<<<grid, 256, SMEM_BYTES>>>(N, M);

    post_kernel<<<M, 256>>>(X, labels, tni, cali, out, M, ncali, Kn);
}